// round 1
// baseline (speedup 1.0000x reference)
#include <cuda_runtime.h>

#define N_NODES 16384
#define A_ANCH  256
#define D_LAT   32

// Precomputed (1/A) * (anchor_emb @ W1)  and  c[j] = b[j] + (1/A)*sum_a (embeds[a] @ W2)[j]
__device__ float g_M[A_ANCH * D_LAT];   // 32 KB
__device__ float g_c[D_LAT];

// ---------------------------------------------------------------------------
// Kernel 1: precompute g_M and g_c. Grid = 9 blocks x 256 threads.
//   blocks 0..7: 32 rows of M each
//   block 8:     column sums of embeds[:256] -> c
// ---------------------------------------------------------------------------
__global__ __launch_bounds__(256) void precompute_kernel(
    const float* __restrict__ embeds,
    const float* __restrict__ W,       // [64,32] row-major: W1 = rows 0..31, W2 = rows 32..63
    const float* __restrict__ b,       // [32]
    const int*   __restrict__ anchor_ids)
{
    __shared__ float Wsh[D_LAT * D_LAT];   // W1 or W2 (1024 floats)
    __shared__ float esh[32][32];
    __shared__ float ssh[D_LAT];

    const int t   = threadIdx.x;
    const int blk = blockIdx.x;
    const int j   = t & 31;

    if (blk < 8) {
        // load W1 into shared
        #pragma unroll
        for (int i = t; i < D_LAT * D_LAT; i += 256) Wsh[i] = W[i];
        // load 32 anchor rows into shared
        for (int r = t >> 5; r < 32; r += 8) {
            int id = anchor_ids[blk * 32 + r];
            esh[r][j] = embeds[id * D_LAT + j];
        }
        __syncthreads();
        // thread (r, j) computes M[blk*32+r][j], 4 rows per thread
        for (int r = t >> 5; r < 32; r += 8) {
            float acc = 0.f;
            #pragma unroll
            for (int d = 0; d < D_LAT; d++) acc += esh[r][d] * Wsh[d * D_LAT + j];
            g_M[(blk * 32 + r) * D_LAT + j] = acc * (1.0f / 256.0f);
        }
    } else {
        // load W2 into shared
        #pragma unroll
        for (int i = t; i < D_LAT * D_LAT; i += 256) Wsh[i] = W[D_LAT * D_LAT + i];
        if (t < D_LAT) ssh[t] = 0.f;
        __syncthreads();
        // column sums of embeds[0:256]
        {
            int grp = t >> 5;     // 0..7, each covers 32 rows
            float part = 0.f;
            #pragma unroll 4
            for (int i = 0; i < 32; i++)
                part += embeds[(grp * 32 + i) * D_LAT + j];
            atomicAdd(&ssh[j], part);
        }
        __syncthreads();
        if (t < D_LAT) {
            float acc = 0.f;
            #pragma unroll
            for (int d = 0; d < D_LAT; d++) acc += ssh[d] * Wsh[d * D_LAT + t];
            g_c[t] = b[t] + acc * (1.0f / 256.0f);
        }
    }
}

// ---------------------------------------------------------------------------
// Kernel 2: out[n,:] = sum_a dists[a,n] * g_M[a,:]  +  g_c
// Grid 256 blocks x 256 threads. Each block: 64 n values, a-loop split 4 ways.
// f32x2 packed FMAs; M broadcast from SMEM.
// ---------------------------------------------------------------------------
__global__ __launch_bounds__(256) void pnn_main_kernel(
    const float* __restrict__ dists,   // [A, N]
    float*       __restrict__ out)     // [N, D]
{
    __shared__ __align__(16) float Msh[A_ANCH * D_LAT];   // 32 KB

    const int t = threadIdx.x;

    // load M (L2-resident, 32 KB)
    {
        const float4* src = (const float4*)g_M;
        float4*       dst = (float4*)Msh;
        #pragma unroll
        for (int i = 0; i < 8; i++) dst[t + 256 * i] = src[t + 256 * i];
    }
    __syncthreads();

    const int group = t >> 6;                 // 0..3  (a-range owner)
    const int ln    = t & 63;                 // local n
    const int n     = blockIdx.x * 64 + ln;
    const int a0    = group * 64;

    unsigned long long acc[16];
    #pragma unroll
    for (int i = 0; i < 16; i++) acc[i] = 0ULL;   // two packed +0.0f

    #define BODY(dv, aidx) do {                                                   \
        unsigned long long dd_;                                                   \
        asm("mov.b64 %0, {%1, %1};" : "=l"(dd_) : "f"(dv));                       \
        const ulonglong2* mp_ = (const ulonglong2*)(Msh + (aidx) * D_LAT);        \
        _Pragma("unroll")                                                         \
        for (int k_ = 0; k_ < 8; k_++) {                                          \
            ulonglong2 mm_ = mp_[k_];                                             \
            asm("fma.rn.f32x2 %0, %1, %2, %0;"                                    \
                : "+l"(acc[2 * k_])     : "l"(dd_), "l"(mm_.x));                  \
            asm("fma.rn.f32x2 %0, %1, %2, %0;"                                    \
                : "+l"(acc[2 * k_ + 1]) : "l"(dd_), "l"(mm_.y));                  \
        }                                                                         \
    } while (0)

    const float* p = dists + (size_t)a0 * N_NODES + n;
    for (int it = 0; it < 64; it += 4) {
        float d0 = p[0];
        float d1 = p[(size_t)N_NODES];
        float d2 = p[2 * (size_t)N_NODES];
        float d3 = p[3 * (size_t)N_NODES];
        p += 4 * (size_t)N_NODES;
        BODY(d0, a0 + it + 0);
        BODY(d1, a0 + it + 1);
        BODY(d2, a0 + it + 2);
        BODY(d3, a0 + it + 3);
    }
    #undef BODY

    // ---- reduction across the 4 a-groups through SMEM (reuse Msh) ----
    __syncthreads();
    {
        unsigned long long* P = (unsigned long long*)Msh;
        #pragma unroll
        for (int i = 0; i < 16; i++) P[group * 1024 + ln * 16 + i] = acc[i];
    }
    __syncthreads();

    {
        const float4* c4  = (const float4*)g_c;
        const float4* M4f = (const float4*)Msh;
        float4*       o4  = (float4*)out;
        #pragma unroll
        for (int i = t; i < 512; i += 256) {
            float4 v0 = M4f[i];
            float4 v1 = M4f[512 + i];
            float4 v2 = M4f[1024 + i];
            float4 v3 = M4f[1536 + i];
            float4 cc = c4[i & 7];
            float4 r;
            r.x = v0.x + v1.x + v2.x + v3.x + cc.x;
            r.y = v0.y + v1.y + v2.y + v3.y + cc.y;
            r.z = v0.z + v1.z + v2.z + v3.z + cc.z;
            r.w = v0.w + v1.w + v2.w + v3.w + cc.w;
            o4[blockIdx.x * 512 + i] = r;
        }
    }
}

extern "C" void kernel_launch(void* const* d_in, const int* in_sizes, int n_in,
                              void* d_out, int out_size)
{
    const float* embeds     = (const float*)d_in[0];
    const float* dists      = (const float*)d_in[1];
    const float* W_hidden   = (const float*)d_in[2];
    const float* b_hidden   = (const float*)d_in[3];
    const int*   anchor_ids = (const int*)  d_in[4];
    float*       out        = (float*)d_out;

    precompute_kernel<<<9, 256>>>(embeds, W_hidden, b_hidden, anchor_ids);
    pnn_main_kernel<<<N_NODES / 64, 256>>>(dists, out);
}

// round 2
// speedup vs baseline: 1.2448x; 1.2448x over previous
#include <cuda_runtime.h>

#define N_NODES 16384
#define A_ANCH  256
#define D_LAT   32

// Precomputed (1/A) * (anchor_emb @ W1)  and  c[j] = b[j] + (1/A)*sum_a (embeds[a] @ W2)[j]
__device__ float g_M[A_ANCH * D_LAT];   // 32 KB
__device__ float g_c[D_LAT];

// ---------------------------------------------------------------------------
// Kernel 1: precompute g_M and g_c. Grid = 9 blocks x 256 threads.
// ---------------------------------------------------------------------------
__global__ __launch_bounds__(256) void precompute_kernel(
    const float* __restrict__ embeds,
    const float* __restrict__ W,       // [64,32] row-major: W1 = rows 0..31, W2 = rows 32..63
    const float* __restrict__ b,       // [32]
    const int*   __restrict__ anchor_ids)
{
    __shared__ float Wsh[D_LAT * D_LAT];
    __shared__ float esh[32][32];
    __shared__ float ssh[D_LAT];

    const int t   = threadIdx.x;
    const int blk = blockIdx.x;
    const int j   = t & 31;

    if (blk < 8) {
        #pragma unroll
        for (int i = t; i < D_LAT * D_LAT; i += 256) Wsh[i] = W[i];
        for (int r = t >> 5; r < 32; r += 8) {
            int id = anchor_ids[blk * 32 + r];
            esh[r][j] = embeds[id * D_LAT + j];
        }
        __syncthreads();
        for (int r = t >> 5; r < 32; r += 8) {
            float acc = 0.f;
            #pragma unroll
            for (int d = 0; d < D_LAT; d++) acc += esh[r][d] * Wsh[d * D_LAT + j];
            g_M[(blk * 32 + r) * D_LAT + j] = acc * (1.0f / 256.0f);
        }
    } else {
        #pragma unroll
        for (int i = t; i < D_LAT * D_LAT; i += 256) Wsh[i] = W[D_LAT * D_LAT + i];
        if (t < D_LAT) ssh[t] = 0.f;
        __syncthreads();
        {
            int grp = t >> 5;
            float part = 0.f;
            #pragma unroll 4
            for (int i = 0; i < 32; i++)
                part += embeds[(grp * 32 + i) * D_LAT + j];
            atomicAdd(&ssh[j], part);
        }
        __syncthreads();
        if (t < D_LAT) {
            float acc = 0.f;
            #pragma unroll
            for (int d = 0; d < D_LAT; d++) acc += ssh[d] * Wsh[d * D_LAT + t];
            g_c[t] = b[t] + acc * (1.0f / 256.0f);
        }
    }
}

// ---------------------------------------------------------------------------
// Kernel 2: out[n,:] = sum_a dists[a,n] * g_M[a,:]  +  g_c
//
// Block = 256 threads = 16 n-slots x 2 col-halves x 8 a-groups.
//   - thread computes a 4n x 16col register tile (32 packed f32x2 accs)
//   - warp w == a-group w (M reads are pure SMEM broadcasts)
//   - dists loads are LDG.128 with prefetch depth 4
//   - 8 a-group partials reduced by a log2 SMEM tree (b64, conflict-free)
// Grid = 256 blocks x 64 n each; 2 blocks/SM -> whole grid resident in 1 wave.
// ---------------------------------------------------------------------------
__global__ __launch_bounds__(256, 2) void pnn_main_kernel(
    const float* __restrict__ dists,   // [A, N]
    float*       __restrict__ out)     // [N, D]
{
    __shared__ __align__(16) unsigned long long sh[4096];   // 32 KB (M, then reduction)
    float* Msh = (float*)sh;

    const int t = threadIdx.x;

    // load M (32 KB) into shared
    {
        const float4* src = (const float4*)g_M;
        float4*       dst = (float4*)Msh;
        #pragma unroll
        for (int i = 0; i < 8; i++) dst[t + 256 * i] = src[t + 256 * i];
    }
    __syncthreads();

    const int slot  = t & 15;          // n-slot within block
    const int half  = (t >> 4) & 1;    // column half (0: cols 0-15, 1: cols 16-31)
    const int group = t >> 5;          // a-group == warp id
    const int n0    = blockIdx.x * 64 + slot * 4;
    const int a0    = group * 32;

    unsigned long long acc[32];        // [n][k] : n in 0..3, k in 0..7 (2 cols each)
    #pragma unroll
    for (int i = 0; i < 32; i++) acc[i] = 0ULL;

    const float* dp   = dists + (size_t)a0 * N_NODES + n0;
    const float* mrow = Msh + a0 * D_LAT + half * 16;

    float4 pf[4];
    #pragma unroll
    for (int i = 0; i < 4; i++)
        pf[i] = *(const float4*)(dp + (size_t)i * N_NODES);

    #pragma unroll 2
    for (int it = 0; it < 32; it += 4) {
        #pragma unroll
        for (int u = 0; u < 4; u++) {
            float4 d = pf[u];
            int nx = (it + u + 4) & 31;            // wrapped (value unused on last round)
            pf[u] = *(const float4*)(dp + (size_t)nx * N_NODES);

            unsigned long long dd0, dd1, dd2, dd3;
            asm("mov.b64 %0,{%1,%1};" : "=l"(dd0) : "f"(d.x));
            asm("mov.b64 %0,{%1,%1};" : "=l"(dd1) : "f"(d.y));
            asm("mov.b64 %0,{%1,%1};" : "=l"(dd2) : "f"(d.z));
            asm("mov.b64 %0,{%1,%1};" : "=l"(dd3) : "f"(d.w));

            const ulonglong2* mp = (const ulonglong2*)(mrow + (it + u) * D_LAT);
            ulonglong2 m0 = mp[0], m1 = mp[1], m2 = mp[2], m3 = mp[3];

            #define FMA8(nn, dd)                                                          \
                asm("fma.rn.f32x2 %0,%1,%2,%0;" : "+l"(acc[(nn)*8+0]) : "l"(dd), "l"(m0.x)); \
                asm("fma.rn.f32x2 %0,%1,%2,%0;" : "+l"(acc[(nn)*8+1]) : "l"(dd), "l"(m0.y)); \
                asm("fma.rn.f32x2 %0,%1,%2,%0;" : "+l"(acc[(nn)*8+2]) : "l"(dd), "l"(m1.x)); \
                asm("fma.rn.f32x2 %0,%1,%2,%0;" : "+l"(acc[(nn)*8+3]) : "l"(dd), "l"(m1.y)); \
                asm("fma.rn.f32x2 %0,%1,%2,%0;" : "+l"(acc[(nn)*8+4]) : "l"(dd), "l"(m2.x)); \
                asm("fma.rn.f32x2 %0,%1,%2,%0;" : "+l"(acc[(nn)*8+5]) : "l"(dd), "l"(m2.y)); \
                asm("fma.rn.f32x2 %0,%1,%2,%0;" : "+l"(acc[(nn)*8+6]) : "l"(dd), "l"(m3.x)); \
                asm("fma.rn.f32x2 %0,%1,%2,%0;" : "+l"(acc[(nn)*8+7]) : "l"(dd), "l"(m3.y));

            FMA8(0, dd0)
            FMA8(1, dd1)
            FMA8(2, dd2)
            FMA8(3, dd3)
            #undef FMA8
        }
    }

    // ---- log2 tree reduction over the 8 a-groups ----
    __syncthreads();   // done reading M; sh is reusable

    #pragma unroll
    for (int s = 128; s >= 32; s >>= 1) {
        if (t >= s && t < 2 * s) {
            #pragma unroll
            for (int i = 0; i < 32; i++) sh[i * s + (t - s)] = acc[i];
        }
        __syncthreads();
        if (t < s) {
            #pragma unroll
            for (int i = 0; i < 32; i++)
                asm("add.rn.f32x2 %0,%0,%1;" : "+l"(acc[i]) : "l"(sh[i * s + t]));
        }
        __syncthreads();
    }

    // ---- epilogue: threads 0..31 hold final sums for the whole block ----
    if (t < 32) {
        const unsigned long long* c64 = (const unsigned long long*)g_c;
        unsigned long long cc[8];
        #pragma unroll
        for (int k = 0; k < 8; k++) cc[k] = c64[half * 8 + k];
        #pragma unroll
        for (int i = 0; i < 32; i++)
            asm("add.rn.f32x2 %0,%0,%1;" : "+l"(acc[i]) : "l"(cc[i & 7]));

        #pragma unroll
        for (int n = 0; n < 4; n++) {
            ulonglong2* op = (ulonglong2*)(out + (size_t)(n0 + n) * D_LAT + half * 16);
            #pragma unroll
            for (int j = 0; j < 4; j++) {
                ulonglong2 v;
                v.x = acc[n * 8 + 2 * j];
                v.y = acc[n * 8 + 2 * j + 1];
                op[j] = v;
            }
        }
    }
}

extern "C" void kernel_launch(void* const* d_in, const int* in_sizes, int n_in,
                              void* d_out, int out_size)
{
    const float* embeds     = (const float*)d_in[0];
    const float* dists      = (const float*)d_in[1];
    const float* W_hidden   = (const float*)d_in[2];
    const float* b_hidden   = (const float*)d_in[3];
    const int*   anchor_ids = (const int*)  d_in[4];
    float*       out        = (float*)d_out;

    precompute_kernel<<<9, 256>>>(embeds, W_hidden, b_hidden, anchor_ids);
    pnn_main_kernel<<<N_NODES / 64, 256>>>(dists, out);
}